// round 1
// baseline (speedup 1.0000x reference)
#include <cuda_runtime.h>
#include <cuda_bf16.h>
#include <cstddef>

// Problem constants
#define B_  256
#define T_  100
#define I_  1024
#define H_  2048
#define O_  10
#define M1  (B_ * T_)   // 25600

// Scratch (allocation-free rule: __device__ globals)
__device__ float g_xin[(size_t)M1 * H_];          // [b*T + t][H]  input projection
__device__ float g_hall[(size_t)T_ * B_ * H_];    // [t][b][H]     hidden states

// ---------------------------------------------------------------------------
// 64x64x16 fp32 tiled GEMM: C[M,N] = A[M,K] @ Bm[K,N]   (row-major)
// 256 threads, each computes a 4x4 micro-tile.
// ---------------------------------------------------------------------------
#define BM 64
#define BN 64
#define BK 16

__global__ void __launch_bounds__(256) gemm_xin_kernel(
    const float* __restrict__ A,    // x  [M1, I_]
    const float* __restrict__ Bm)   // Win [I_, H_]
{
    __shared__ float As[BK][BM];
    __shared__ float Bs[BK][BN];

    const int tid = threadIdx.x;
    const int tx = tid & 15;
    const int ty = tid >> 4;
    const int rowBase = blockIdx.y * BM;
    const int colBase = blockIdx.x * BN;

    const int a_row = tid >> 2;          // 0..63
    const int a_col = (tid & 3) << 2;    // 0,4,8,12
    const int b_row = tid >> 4;          // 0..15
    const int b_col = (tid & 15) << 2;   // 0..60

    float acc[4][4] = {};

    const float* Aptr = A + (size_t)(rowBase + a_row) * I_ + a_col;
    const float* Bptr = Bm + (size_t)b_row * H_ + colBase + b_col;

    for (int k0 = 0; k0 < I_; k0 += BK) {
        float4 av = *(const float4*)(Aptr + k0);
        As[a_col + 0][a_row] = av.x;
        As[a_col + 1][a_row] = av.y;
        As[a_col + 2][a_row] = av.z;
        As[a_col + 3][a_row] = av.w;
        float4 bv = *(const float4*)(Bptr + (size_t)k0 * H_);
        *(float4*)&Bs[b_row][b_col] = bv;
        __syncthreads();

        #pragma unroll
        for (int kk = 0; kk < BK; kk++) {
            float4 a = *(const float4*)&As[kk][ty << 2];
            float4 b = *(const float4*)&Bs[kk][tx << 2];
            float ar[4] = {a.x, a.y, a.z, a.w};
            float br[4] = {b.x, b.y, b.z, b.w};
            #pragma unroll
            for (int i = 0; i < 4; i++)
                #pragma unroll
                for (int j = 0; j < 4; j++)
                    acc[i][j] += ar[i] * br[j];
        }
        __syncthreads();
    }

    #pragma unroll
    for (int i = 0; i < 4; i++) {
        float4 v = make_float4(acc[i][0], acc[i][1], acc[i][2], acc[i][3]);
        *(float4*)&g_xin[(size_t)(rowBase + (ty << 2) + i) * H_ + colBase + (tx << 2)] = v;
    }
}

// ---------------------------------------------------------------------------
// One recurrence step: h_t = tanh(xin_t + h_{t-1} @ W)
// M=256 (=B), N=K=2048 (=H). Grid: (32, 4) = 128 blocks.
// ---------------------------------------------------------------------------
__global__ void __launch_bounds__(256) step_kernel(
    const float* __restrict__ h0,
    const float* __restrict__ W,
    int t)
{
    __shared__ float As[BK][BM];
    __shared__ float Bs[BK][BN];

    const float* A = (t == 0) ? h0 : (g_hall + (size_t)(t - 1) * B_ * H_);
    float* hout = g_hall + (size_t)t * B_ * H_;

    const int tid = threadIdx.x;
    const int tx = tid & 15;
    const int ty = tid >> 4;
    const int rowBase = blockIdx.y * BM;   // b offset
    const int colBase = blockIdx.x * BN;   // h-dim offset

    const int a_row = tid >> 2;
    const int a_col = (tid & 3) << 2;
    const int b_row = tid >> 4;
    const int b_col = (tid & 15) << 2;

    float acc[4][4] = {};

    const float* Aptr = A + (size_t)(rowBase + a_row) * H_ + a_col;
    const float* Bptr = W + (size_t)b_row * H_ + colBase + b_col;

    for (int k0 = 0; k0 < H_; k0 += BK) {
        float4 av = *(const float4*)(Aptr + k0);
        As[a_col + 0][a_row] = av.x;
        As[a_col + 1][a_row] = av.y;
        As[a_col + 2][a_row] = av.z;
        As[a_col + 3][a_row] = av.w;
        float4 bv = *(const float4*)(Bptr + (size_t)k0 * H_);
        *(float4*)&Bs[b_row][b_col] = bv;
        __syncthreads();

        #pragma unroll
        for (int kk = 0; kk < BK; kk++) {
            float4 a = *(const float4*)&As[kk][ty << 2];
            float4 b = *(const float4*)&Bs[kk][tx << 2];
            float ar[4] = {a.x, a.y, a.z, a.w};
            float br[4] = {b.x, b.y, b.z, b.w};
            #pragma unroll
            for (int i = 0; i < 4; i++)
                #pragma unroll
                for (int j = 0; j < 4; j++)
                    acc[i][j] += ar[i] * br[j];
        }
        __syncthreads();
    }

    // Epilogue: h = tanh(xin[b][t][:] + acc);  xin is [b*T + t][H]
    #pragma unroll
    for (int i = 0; i < 4; i++) {
        const int b = rowBase + (ty << 2) + i;
        const int c = colBase + (tx << 2);
        const float* xrow = &g_xin[((size_t)b * T_ + t) * H_ + c];
        float4 xv = *(const float4*)xrow;
        float4 v;
        v.x = tanhf(xv.x + acc[i][0]);
        v.y = tanhf(xv.y + acc[i][1]);
        v.z = tanhf(xv.z + acc[i][2]);
        v.w = tanhf(xv.w + acc[i][3]);
        *(float4*)&hout[(size_t)b * H_ + c] = v;
    }
}

// ---------------------------------------------------------------------------
// Output head: out[b,t,o] = h_all[t,b,:] . lin_w[o,:] + lin_b[o]
// One block per (t,b); 256 threads; warp-shuffle reduce.
// ---------------------------------------------------------------------------
__global__ void __launch_bounds__(256) out_kernel(
    const float* __restrict__ lin_w,
    const float* __restrict__ lin_b,
    float* __restrict__ out)
{
    const int bt = blockIdx.x;       // 0 .. T_*B_-1
    const int t = bt / B_;
    const int b = bt % B_;
    const int tid = threadIdx.x;

    const float* hrow = g_hall + ((size_t)t * B_ + b) * H_;

    float hreg[H_ / 256];
    #pragma unroll
    for (int i = 0; i < H_ / 256; i++)
        hreg[i] = hrow[i * 256 + tid];

    float acc[O_];
    #pragma unroll
    for (int o = 0; o < O_; o++) {
        float s = 0.f;
        #pragma unroll
        for (int i = 0; i < H_ / 256; i++)
            s += hreg[i] * lin_w[(size_t)o * H_ + i * 256 + tid];
        acc[o] = s;
    }

    #pragma unroll
    for (int off = 16; off > 0; off >>= 1)
        #pragma unroll
        for (int o = 0; o < O_; o++)
            acc[o] += __shfl_xor_sync(0xFFFFFFFFu, acc[o], off);

    __shared__ float wsum[8][O_];
    const int lane = tid & 31;
    const int w = tid >> 5;
    if (lane == 0)
        #pragma unroll
        for (int o = 0; o < O_; o++)
            wsum[w][o] = acc[o];
    __syncthreads();

    if (tid < O_) {
        float s = lin_b[tid];
        #pragma unroll
        for (int ww = 0; ww < 8; ww++)
            s += wsum[ww][tid];
        out[((size_t)b * T_ + t) * O_ + tid] = s;
    }
}

// ---------------------------------------------------------------------------
extern "C" void kernel_launch(void* const* d_in, const int* in_sizes, int n_in,
                              void* d_out, int out_size)
{
    const float* x     = (const float*)d_in[0];  // [B,T,I]
    const float* h0    = (const float*)d_in[1];  // [B,H]
    const float* Win   = (const float*)d_in[2];  // [I,H]
    const float* W     = (const float*)d_in[3];  // [H,H]
    const float* lin_w = (const float*)d_in[4];  // [O,H]
    const float* lin_b = (const float*)d_in[5];  // [O]
    float* out = (float*)d_out;                  // [B,T,O]

    // 1) Input projection: g_xin = x @ Win
    dim3 g1(H_ / BN, M1 / BM);   // (32, 400)
    gemm_xin_kernel<<<g1, 256>>>(x, Win);

    // 2) Recurrence: 100 sequential steps
    dim3 g2(H_ / BN, B_ / BM);   // (32, 4) = 128 blocks
    for (int t = 0; t < T_; t++)
        step_kernel<<<g2, 256>>>(h0, W, t);

    // 3) Output head over all (t, b)
    out_kernel<<<T_ * B_, 256>>>(lin_w, lin_b, out);
}

// round 3
// speedup vs baseline: 2.1791x; 2.1791x over previous
#include <cuda_runtime.h>
#include <cuda_bf16.h>
#include <cstdint>
#include <cstddef>

// ---------------------------------------------------------------------------
// Problem constants
// ---------------------------------------------------------------------------
#define B_  256
#define T_  100
#define I_  1024
#define H_  2048
#define O_  10
#define M1  (B_ * T_)   // 25600

// GEMM tiling
#define BM 64
#define BN 64
#define BK 32
#define STRIDE 40       // padded bf16 row stride in smem (conflict-free frags)

// ---------------------------------------------------------------------------
// Device scratch
// ---------------------------------------------------------------------------
__device__ float g_xin [(size_t)T_ * B_ * H_];         // [t][b][h]
__device__ float g_hall[(size_t)T_ * B_ * H_];         // [t][b][h]
__device__ __nv_bfloat16 g_WinT_hi[(size_t)H_ * I_];   // WinT[h][i] = Win[i][h]
__device__ __nv_bfloat16 g_WinT_lo[(size_t)H_ * I_];
__device__ __nv_bfloat16 g_WT_hi[(size_t)H_ * H_];     // WT[n][k] = W[k][n]
__device__ __nv_bfloat16 g_WT_lo[(size_t)H_ * H_];

// ---------------------------------------------------------------------------
// mma.sync m16n8k16 bf16 (baseline PTX, works at compute_103)
// ---------------------------------------------------------------------------
__device__ __forceinline__ void mma_bf16(float* d, const uint32_t* a, uint32_t b0, uint32_t b1) {
    asm volatile(
        "mma.sync.aligned.m16n8k16.row.col.f32.bf16.bf16.f32 "
        "{%0,%1,%2,%3}, {%4,%5,%6,%7}, {%8,%9}, {%0,%1,%2,%3};"
        : "+f"(d[0]), "+f"(d[1]), "+f"(d[2]), "+f"(d[3])
        : "r"(a[0]), "r"(a[1]), "r"(a[2]), "r"(a[3]), "r"(b0), "r"(b1));
}

__device__ __forceinline__ void split2(float v, __nv_bfloat16& h, __nv_bfloat16& l) {
    h = __float2bfloat16(v);
    l = __float2bfloat16(v - __bfloat162float(h));
}

// ---------------------------------------------------------------------------
// Weight transpose + hi/lo split:  dst[n][k] = src[k][n]
// which==0: Win -> WinT,  which==1: W -> WT
// ---------------------------------------------------------------------------
__global__ void transpose_decomp_kernel(const float* __restrict__ src, int R, int C, int which) {
    __nv_bfloat16* dhi = which ? g_WT_hi : g_WinT_hi;
    __nv_bfloat16* dlo = which ? g_WT_lo : g_WinT_lo;
    __shared__ float tile[32][33];
    const int bx = blockIdx.x * 32;   // col base (n)
    const int by = blockIdx.y * 32;   // row base (k)
    const int tx = threadIdx.x, ty = threadIdx.y;
    #pragma unroll
    for (int j = 0; j < 32; j += 8)
        tile[ty + j][tx] = src[(size_t)(by + ty + j) * C + bx + tx];
    __syncthreads();
    #pragma unroll
    for (int j = 0; j < 32; j += 8) {
        float v = tile[tx][ty + j];
        size_t o = (size_t)(bx + ty + j) * R + by + tx;
        __nv_bfloat16 h, l; split2(v, h, l);
        dhi[o] = h; dlo[o] = l;
    }
}

// ---------------------------------------------------------------------------
// bf16x3 GEMM via mma.sync.  C = A(fp32, split on the fly) @ B(pre-split)^T
//   !IS_STEP: g_xin[t][b][:] = x @ Win          (Asrc = x,      Bt = WinT)
//   IS_STEP : h_t = tanh(xin_t + h_{t-1} @ W)   (Asrc = h_prev, Bt = WT)
// CTA = 64x64, 256 threads, 8 warps (4 m x 2 n), warp tile 16x32.
// ---------------------------------------------------------------------------
template<int KTOT, bool IS_STEP>
__global__ void __launch_bounds__(256) mma_gemm_kernel(
    const float* __restrict__ Asrc,
    const __nv_bfloat16* __restrict__ Bt_hi,
    const __nv_bfloat16* __restrict__ Bt_lo,
    int t)
{
    constexpr int NK = KTOT / BK;

    __shared__ __nv_bfloat16 sAh[2][BM * STRIDE];
    __shared__ __nv_bfloat16 sAl[2][BM * STRIDE];
    __shared__ __nv_bfloat16 sBh[2][BN * STRIDE];
    __shared__ __nv_bfloat16 sBl[2][BN * STRIDE];

    const int tid  = threadIdx.x;
    const int wid  = tid >> 5;
    const int lane = tid & 31;
    const int g    = lane >> 2;     // groupID
    const int tg   = lane & 3;      // thread-in-group
    const int wm   = wid & 3;       // warp m index (16 rows each)
    const int wn   = wid >> 2;      // warp n index (32 cols each)

    const int rowBase = blockIdx.y * BM;
    const int colBase = blockIdx.x * BN;

    // A loader: 2 segments of 4 floats per thread
    const int a_r  = tid >> 3;            // 0..31 (second seg: +32)
    const int a_c  = (tid & 7) << 2;      // 0,4,..,28
    // B loader: 1 uint4 (8 bf16) per thread per tile
    const int b_r  = tid >> 2;            // 0..63
    const int b_c  = (tid & 3) << 3;      // 0,8,16,24

    float d[4][4] = {};                   // 4 n-tiles x (d0..d3)

    float4 av[2];
    uint4  bvh, bvl;

    // ---- prefetch chunk 0 ----
    {
        const float* Ap = Asrc + (size_t)(rowBase + a_r) * KTOT + a_c;
        av[0] = *(const float4*)(Ap);
        av[1] = *(const float4*)(Ap + (size_t)32 * KTOT);
        const size_t gb = (size_t)(colBase + b_r) * KTOT + b_c;
        bvh = *(const uint4*)(Bt_hi + gb);
        bvl = *(const uint4*)(Bt_lo + gb);
    }

    #pragma unroll 1
    for (int kc = 0; kc < NK; kc++) {
        const int buf = kc & 1;
        // ---- store prefetched regs to smem[buf] ----
        {
            #pragma unroll
            for (int i = 0; i < 2; i++) {
                const float4 v = av[i];
                __nv_bfloat16 h0,l0,h1,l1,h2,l2,h3,l3;
                split2(v.x, h0, l0); split2(v.y, h1, l1);
                split2(v.z, h2, l2); split2(v.w, h3, l3);
                const int o = (a_r + i * 32) * STRIDE + a_c;
                __nv_bfloat162* ph = (__nv_bfloat162*)&sAh[buf][o];
                __nv_bfloat162* pl = (__nv_bfloat162*)&sAl[buf][o];
                ph[0] = __halves2bfloat162(h0, h1);
                ph[1] = __halves2bfloat162(h2, h3);
                pl[0] = __halves2bfloat162(l0, l1);
                pl[1] = __halves2bfloat162(l2, l3);
            }
            const int o = b_r * STRIDE + b_c;
            *(uint4*)&sBh[buf][o] = bvh;
            *(uint4*)&sBl[buf][o] = bvl;
        }
        __syncthreads();

        // ---- prefetch chunk kc+1 ----
        if (kc + 1 < NK) {
            const int k0 = (kc + 1) * BK;
            const float* Ap = Asrc + (size_t)(rowBase + a_r) * KTOT + k0 + a_c;
            av[0] = *(const float4*)(Ap);
            av[1] = *(const float4*)(Ap + (size_t)32 * KTOT);
            const size_t gb = (size_t)(colBase + b_r) * KTOT + k0 + b_c;
            bvh = *(const uint4*)(Bt_hi + gb);
            bvl = *(const uint4*)(Bt_lo + gb);
        }

        // ---- compute on smem[buf] ----
        const int ar0 = (wm * 16 + g) * STRIDE;
        const int ar1 = ar0 + 8 * STRIDE;
        #pragma unroll
        for (int kh = 0; kh < 2; kh++) {
            const int kb = kh * 16 + 2 * tg;
            uint32_t ah[4], al[4];
            ah[0] = *(const uint32_t*)&sAh[buf][ar0 + kb];
            ah[1] = *(const uint32_t*)&sAh[buf][ar1 + kb];
            ah[2] = *(const uint32_t*)&sAh[buf][ar0 + kb + 8];
            ah[3] = *(const uint32_t*)&sAh[buf][ar1 + kb + 8];
            al[0] = *(const uint32_t*)&sAl[buf][ar0 + kb];
            al[1] = *(const uint32_t*)&sAl[buf][ar1 + kb];
            al[2] = *(const uint32_t*)&sAl[buf][ar0 + kb + 8];
            al[3] = *(const uint32_t*)&sAl[buf][ar1 + kb + 8];
            #pragma unroll
            for (int j = 0; j < 4; j++) {
                const int nb = (wn * 32 + j * 8 + g) * STRIDE + kb;
                uint32_t bh0 = *(const uint32_t*)&sBh[buf][nb];
                uint32_t bh1 = *(const uint32_t*)&sBh[buf][nb + 8];
                uint32_t bl0 = *(const uint32_t*)&sBl[buf][nb];
                uint32_t bl1 = *(const uint32_t*)&sBl[buf][nb + 8];
                mma_bf16(d[j], ah, bh0, bh1);
                mma_bf16(d[j], ah, bl0, bl1);
                mma_bf16(d[j], al, bh0, bh1);
            }
        }
        __syncthreads();
    }

    // ---- epilogue ----
    const int r0 = rowBase + wm * 16 + g;      // global m row (d0,d1)
    const int r1 = r0 + 8;                     // (d2,d3)
    #pragma unroll
    for (int j = 0; j < 4; j++) {
        const int col = colBase + wn * 32 + j * 8 + 2 * tg;
        if (IS_STEP) {
            // rows are batch indices
            const size_t o0 = ((size_t)t * B_ + r0) * H_ + col;
            const size_t o1 = ((size_t)t * B_ + r1) * H_ + col;
            float2 x0 = *(const float2*)&g_xin[o0];
            float2 x1 = *(const float2*)&g_xin[o1];
            float2 h0 = make_float2(tanhf(x0.x + d[j][0]), tanhf(x0.y + d[j][1]));
            float2 h1 = make_float2(tanhf(x1.x + d[j][2]), tanhf(x1.y + d[j][3]));
            *(float2*)&g_hall[o0] = h0;
            *(float2*)&g_hall[o1] = h1;
        } else {
            // rows are m = b*T + t
            const int bb0 = r0 / T_, tt0 = r0 - bb0 * T_;
            const int bb1 = r1 / T_, tt1 = r1 - bb1 * T_;
            const size_t o0 = ((size_t)tt0 * B_ + bb0) * H_ + col;
            const size_t o1 = ((size_t)tt1 * B_ + bb1) * H_ + col;
            *(float2*)&g_xin[o0] = make_float2(d[j][0], d[j][1]);
            *(float2*)&g_xin[o1] = make_float2(d[j][2], d[j][3]);
        }
    }
}

// ---------------------------------------------------------------------------
// Output head: out[b,t,o] = h_all[t,b,:] . lin_w[o,:] + lin_b[o]
// ---------------------------------------------------------------------------
__global__ void __launch_bounds__(256) out_kernel(
    const float* __restrict__ lin_w,
    const float* __restrict__ lin_b,
    float* __restrict__ out)
{
    const int bt = blockIdx.x;
    const int t = bt / B_;
    const int b = bt % B_;
    const int tid = threadIdx.x;

    const float* hrow = g_hall + ((size_t)t * B_ + b) * H_;

    float hreg[H_ / 256];
    #pragma unroll
    for (int i = 0; i < H_ / 256; i++)
        hreg[i] = hrow[i * 256 + tid];

    float acc[O_];
    #pragma unroll
    for (int o = 0; o < O_; o++) {
        float s = 0.f;
        #pragma unroll
        for (int i = 0; i < H_ / 256; i++)
            s += hreg[i] * lin_w[(size_t)o * H_ + i * 256 + tid];
        acc[o] = s;
    }

    #pragma unroll
    for (int off = 16; off > 0; off >>= 1)
        #pragma unroll
        for (int o = 0; o < O_; o++)
            acc[o] += __shfl_xor_sync(0xFFFFFFFFu, acc[o], off);

    __shared__ float wsum[8][O_];
    const int lane = tid & 31;
    const int w = tid >> 5;
    if (lane == 0)
        #pragma unroll
        for (int o = 0; o < O_; o++)
            wsum[w][o] = acc[o];
    __syncthreads();

    if (tid < O_) {
        float s = lin_b[tid];
        #pragma unroll
        for (int ww = 0; ww < 8; ww++)
            s += wsum[ww][tid];
        out[((size_t)b * T_ + t) * O_ + tid] = s;
    }
}

// ---------------------------------------------------------------------------
extern "C" void kernel_launch(void* const* d_in, const int* in_sizes, int n_in,
                              void* d_out, int out_size)
{
    const float* x     = (const float*)d_in[0];  // [B,T,I]
    const float* h0    = (const float*)d_in[1];  // [B,H]
    const float* Win   = (const float*)d_in[2];  // [I,H]
    const float* W     = (const float*)d_in[3];  // [H,H]
    const float* lin_w = (const float*)d_in[4];  // [O,H]
    const float* lin_b = (const float*)d_in[5];  // [O]
    float* out = (float*)d_out;                  // [B,T,O]

    // Device-global addresses (host side)
    __nv_bfloat16 *winT_hi, *winT_lo, *wT_hi, *wT_lo;
    float *hall;
    cudaGetSymbolAddress((void**)&winT_hi, g_WinT_hi);
    cudaGetSymbolAddress((void**)&winT_lo, g_WinT_lo);
    cudaGetSymbolAddress((void**)&wT_hi, g_WT_hi);
    cudaGetSymbolAddress((void**)&wT_lo, g_WT_lo);
    cudaGetSymbolAddress((void**)&hall, g_hall);

    // Prologue: weight transpose + split (one-time per launch)
    transpose_decomp_kernel<<<dim3(H_ / 32, I_ / 32), dim3(32, 8)>>>(Win, I_, H_, 0);
    transpose_decomp_kernel<<<dim3(H_ / 32, H_ / 32), dim3(32, 8)>>>(W, H_, H_, 1);

    // Input projection: g_xin = x @ Win  (stored [t][b][h])
    mma_gemm_kernel<I_, false><<<dim3(H_ / BN, M1 / BM), 256>>>(x, winT_hi, winT_lo, 0);

    // Recurrence: 100 sequential steps
    for (int t = 0; t < T_; t++) {
        const float* Aprev = (t == 0) ? h0 : (hall + (size_t)(t - 1) * B_ * H_);
        mma_gemm_kernel<H_, true><<<dim3(H_ / BN, B_ / BM), 256>>>(Aprev, wT_hi, wT_lo, t);
    }

    // Output head
    out_kernel<<<T_ * B_, 256>>>(lin_w, lin_b, out);
}

// round 4
// speedup vs baseline: 2.4889x; 1.1422x over previous
#include <cuda_runtime.h>
#include <cuda_bf16.h>
#include <cstdint>
#include <cstddef>

// ---------------------------------------------------------------------------
// Problem constants
// ---------------------------------------------------------------------------
#define B_  256
#define T_  100
#define I_  1024
#define H_  2048
#define O_  10
#define M1  (B_ * T_)   // 25600

// GEMM tiling
#define BM 64
#define BN 64
#define BK 32
#define STRIDE 40                    // padded bf16 row stride in smem
#define NSTAGE 4
#define SLOT   (BM * STRIDE)         // 2560 elems per array per stage
#define ABYTES (NSTAGE * SLOT * 2)   // 20480 bytes per operand array
#define SMEM_BYTES (4 * ABYTES)      // 81920 bytes

#define NBLK_STEP 128                // persistent grid size

// ---------------------------------------------------------------------------
// Device scratch
// ---------------------------------------------------------------------------
__device__ float g_xin [(size_t)T_ * B_ * H_];         // [t][b][h]
__device__ float g_hall[(size_t)T_ * B_ * H_];         // [t][b][h]
__device__ __nv_bfloat16 g_xhi[(size_t)M1 * I_];
__device__ __nv_bfloat16 g_xlo[(size_t)M1 * I_];
__device__ __nv_bfloat16 g_WinT_hi[(size_t)H_ * I_];   // [h][i]
__device__ __nv_bfloat16 g_WinT_lo[(size_t)H_ * I_];
__device__ __nv_bfloat16 g_WT_hi[(size_t)H_ * H_];     // [n][k]
__device__ __nv_bfloat16 g_WT_lo[(size_t)H_ * H_];
__device__ __nv_bfloat16 g_hA_hi[(size_t)B_ * H_], g_hA_lo[(size_t)B_ * H_];
__device__ __nv_bfloat16 g_hB_hi[(size_t)B_ * H_], g_hB_lo[(size_t)B_ * H_];
__device__ unsigned g_bar_count = 0;
__device__ unsigned g_bar_sense = 0;

// ---------------------------------------------------------------------------
// Helpers
// ---------------------------------------------------------------------------
__device__ __forceinline__ uint32_t s2u(const void* p) {
    uint32_t a;
    asm("{ .reg .u64 t; cvta.to.shared.u64 t, %1; cvt.u32.u64 %0, t; }" : "=r"(a) : "l"(p));
    return a;
}
__device__ __forceinline__ void cp16(uint32_t s, const void* g) {
    asm volatile("cp.async.cg.shared.global [%0], [%1], 16;" :: "r"(s), "l"(g));
}
#define CP_COMMIT()  asm volatile("cp.async.commit_group;")
#define CP_WAIT(N)   asm volatile("cp.async.wait_group %0;" :: "n"(N))

__device__ __forceinline__ void mma_bf16(float* d, const uint32_t* a, uint32_t b0, uint32_t b1) {
    asm volatile(
        "mma.sync.aligned.m16n8k16.row.col.f32.bf16.bf16.f32 "
        "{%0,%1,%2,%3}, {%4,%5,%6,%7}, {%8,%9}, {%0,%1,%2,%3};"
        : "+f"(d[0]), "+f"(d[1]), "+f"(d[2]), "+f"(d[3])
        : "r"(a[0]), "r"(a[1]), "r"(a[2]), "r"(a[3]), "r"(b0), "r"(b1));
}
__device__ __forceinline__ void split2(float v, __nv_bfloat16& h, __nv_bfloat16& l) {
    h = __float2bfloat16(v);
    l = __float2bfloat16(v - __bfloat162float(h));
}

// bf16x3 compute on one smem stage: 2 k16 halves x 4 n-tiles x 3 passes
__device__ __forceinline__ void compute_stage(
    const __nv_bfloat16* sAh, const __nv_bfloat16* sAl,
    const __nv_bfloat16* sBh, const __nv_bfloat16* sBl,
    int wm, int wn, int g, int tg, float (*d)[4])
{
    const int ar0 = (wm * 16 + g) * STRIDE;
    const int ar1 = ar0 + 8 * STRIDE;
    #pragma unroll
    for (int kh = 0; kh < 2; kh++) {
        const int kb = kh * 16 + 2 * tg;
        uint32_t ah[4], al[4];
        ah[0] = *(const uint32_t*)&sAh[ar0 + kb];
        ah[1] = *(const uint32_t*)&sAh[ar1 + kb];
        ah[2] = *(const uint32_t*)&sAh[ar0 + kb + 8];
        ah[3] = *(const uint32_t*)&sAh[ar1 + kb + 8];
        al[0] = *(const uint32_t*)&sAl[ar0 + kb];
        al[1] = *(const uint32_t*)&sAl[ar1 + kb];
        al[2] = *(const uint32_t*)&sAl[ar0 + kb + 8];
        al[3] = *(const uint32_t*)&sAl[ar1 + kb + 8];
        #pragma unroll
        for (int j = 0; j < 4; j++) {
            const int nb = (wn * 32 + j * 8 + g) * STRIDE + kb;
            uint32_t bh0 = *(const uint32_t*)&sBh[nb];
            uint32_t bh1 = *(const uint32_t*)&sBh[nb + 8];
            uint32_t bl0 = *(const uint32_t*)&sBl[nb];
            uint32_t bl1 = *(const uint32_t*)&sBl[nb + 8];
            mma_bf16(d[j], ah, bh0, bh1);
            mma_bf16(d[j], ah, bl0, bl1);
            mma_bf16(d[j], al, bh0, bh1);
        }
    }
}

// ---------------------------------------------------------------------------
// Prologue kernels
// ---------------------------------------------------------------------------
__global__ void decomp_kernel(const float* __restrict__ src,
                              __nv_bfloat16* __restrict__ hi,
                              __nv_bfloat16* __restrict__ lo, size_t n4) {
    for (size_t i = (size_t)blockIdx.x * blockDim.x + threadIdx.x; i < n4;
         i += (size_t)gridDim.x * blockDim.x) {
        float4 v = ((const float4*)src)[i];
        __nv_bfloat16 h0, l0, h1, l1, h2, l2, h3, l3;
        split2(v.x, h0, l0); split2(v.y, h1, l1);
        split2(v.z, h2, l2); split2(v.w, h3, l3);
        ((__nv_bfloat162*)hi)[i * 2 + 0] = __halves2bfloat162(h0, h1);
        ((__nv_bfloat162*)hi)[i * 2 + 1] = __halves2bfloat162(h2, h3);
        ((__nv_bfloat162*)lo)[i * 2 + 0] = __halves2bfloat162(l0, l1);
        ((__nv_bfloat162*)lo)[i * 2 + 1] = __halves2bfloat162(l2, l3);
    }
}

// dst[n][k] = src[k][n], split hi/lo
__global__ void transpose_decomp_kernel(const float* __restrict__ src, int R, int C,
                                        __nv_bfloat16* __restrict__ dhi,
                                        __nv_bfloat16* __restrict__ dlo) {
    __shared__ float tile[32][33];
    const int bx = blockIdx.x * 32;
    const int by = blockIdx.y * 32;
    const int tx = threadIdx.x, ty = threadIdx.y;
    #pragma unroll
    for (int j = 0; j < 32; j += 8)
        tile[ty + j][tx] = src[(size_t)(by + ty + j) * C + bx + tx];
    __syncthreads();
    #pragma unroll
    for (int j = 0; j < 32; j += 8) {
        float v = tile[tx][ty + j];
        size_t o = (size_t)(bx + ty + j) * R + by + tx;
        __nv_bfloat16 h, l; split2(v, h, l);
        dhi[o] = h; dlo[o] = l;
    }
}

// ---------------------------------------------------------------------------
// xin GEMM: g_xin[t][b][:] = x @ Win.   A=g_xhi/lo [M1,I], B=g_WinT [H,I]
// ---------------------------------------------------------------------------
__global__ void __launch_bounds__(256) xin_gemm_kernel() {
    extern __shared__ __nv_bfloat16 sm[];
    __nv_bfloat16* pAh = sm;
    __nv_bfloat16* pAl = sm + 1 * NSTAGE * SLOT;
    __nv_bfloat16* pBh = sm + 2 * NSTAGE * SLOT;
    __nv_bfloat16* pBl = sm + 3 * NSTAGE * SLOT;
    const uint32_t sbase = s2u(sm);

    const int tid = threadIdx.x;
    const int wid = tid >> 5, lane = tid & 31;
    const int g = lane >> 2, tg = lane & 3;
    const int wm = wid & 3, wn = wid >> 2;
    const int rowBase = blockIdx.y * BM;
    const int colBase = blockIdx.x * BN;
    const int lr = tid >> 2, lc = (tid & 3) * 8;
    constexpr int NK = I_ / BK;   // 32

    auto issue = [&](int slot, int kc) {
        const int k0 = kc * BK;
        const size_t ga = (size_t)(rowBase + lr) * I_ + k0 + lc;
        const size_t gb = (size_t)(colBase + lr) * I_ + k0 + lc;
        const uint32_t so = (uint32_t)(slot * SLOT + lr * STRIDE + lc) * 2;
        cp16(sbase + 0 * ABYTES + so, g_xhi + ga);
        cp16(sbase + 1 * ABYTES + so, g_xlo + ga);
        cp16(sbase + 2 * ABYTES + so, g_WinT_hi + gb);
        cp16(sbase + 3 * ABYTES + so, g_WinT_lo + gb);
        CP_COMMIT();
    };

    issue(0, 0); issue(1, 1); issue(2, 2);
    float d[4][4] = {};

    #pragma unroll 1
    for (int kc = 0; kc < NK; kc++) {
        CP_WAIT(2);
        __syncthreads();
        if (kc + 3 < NK) issue((kc + 3) & 3, kc + 3);
        const int s = (kc & 3) * SLOT;
        compute_stage(pAh + s, pAl + s, pBh + s, pBl + s, wm, wn, g, tg, d);
    }
    CP_WAIT(0);

    // epilogue: rows m = b*T + t  ->  g_xin[t][b][col]
    const int r0 = rowBase + wm * 16 + g;
    const int r1 = r0 + 8;
    const int bb0 = r0 / T_, tt0 = r0 - bb0 * T_;
    const int bb1 = r1 / T_, tt1 = r1 - bb1 * T_;
    #pragma unroll
    for (int j = 0; j < 4; j++) {
        const int col = colBase + wn * 32 + j * 8 + 2 * tg;
        *(float2*)&g_xin[((size_t)tt0 * B_ + bb0) * H_ + col] = make_float2(d[j][0], d[j][1]);
        *(float2*)&g_xin[((size_t)tt1 * B_ + bb1) * H_ + col] = make_float2(d[j][2], d[j][3]);
    }
}

// ---------------------------------------------------------------------------
// Persistent recurrence kernel: all T steps, grid barrier between steps.
// grid = 128 CTAs (<=148 SMs -> wave-1 co-resident), 256 threads.
// ---------------------------------------------------------------------------
__device__ __forceinline__ void grid_barrier(unsigned target) {
    __threadfence();
    __syncthreads();
    if (threadIdx.x == 0) {
        unsigned a = atomicAdd(&g_bar_count, 1);
        if (a == NBLK_STEP - 1) {
            atomicExch(&g_bar_count, 0);
            atomicExch(&g_bar_sense, target);
        } else {
            while (atomicAdd(&g_bar_sense, 0) < target) { __nanosleep(64); }
        }
    }
    __syncthreads();
}

__global__ void __launch_bounds__(256) step_persistent_kernel() {
    extern __shared__ __nv_bfloat16 sm[];
    __nv_bfloat16* pAh = sm;
    __nv_bfloat16* pAl = sm + 1 * NSTAGE * SLOT;
    __nv_bfloat16* pBh = sm + 2 * NSTAGE * SLOT;
    __nv_bfloat16* pBl = sm + 3 * NSTAGE * SLOT;
    const uint32_t sbase = s2u(sm);

    const int tid = threadIdx.x;
    const int wid = tid >> 5, lane = tid & 31;
    const int g = lane >> 2, tg = lane & 3;
    const int wm = wid & 3, wn = wid >> 2;
    const int bid = blockIdx.x;
    const int rowBase = (bid >> 5) * BM;   // 4 row tiles (B=256)
    const int colBase = (bid & 31) * BN;   // 32 col tiles (H=2048)
    const int lr = tid >> 2, lc = (tid & 3) * 8;
    constexpr int NK = H_ / BK;   // 64

    __shared__ unsigned s_base;
    if (tid == 0) s_base = atomicAdd(&g_bar_sense, 0u);
    __syncthreads();
    const unsigned base = s_base;

    #pragma unroll 1
    for (int t = 0; t < T_; t++) {
        const __nv_bfloat16* ah  = (t & 1) ? g_hB_hi : g_hA_hi;
        const __nv_bfloat16* al  = (t & 1) ? g_hB_lo : g_hA_lo;
        __nv_bfloat16* whi = (t & 1) ? g_hA_hi : g_hB_hi;
        __nv_bfloat16* wlo = (t & 1) ? g_hA_lo : g_hB_lo;

        auto issue = [&](int slot, int kc) {
            const int k0 = kc * BK;
            const size_t ga = (size_t)(rowBase + lr) * H_ + k0 + lc;
            const size_t gb = (size_t)(colBase + lr) * H_ + k0 + lc;
            const uint32_t so = (uint32_t)(slot * SLOT + lr * STRIDE + lc) * 2;
            cp16(sbase + 0 * ABYTES + so, ah + ga);
            cp16(sbase + 1 * ABYTES + so, al + ga);
            cp16(sbase + 2 * ABYTES + so, g_WT_hi + gb);
            cp16(sbase + 3 * ABYTES + so, g_WT_lo + gb);
            CP_COMMIT();
        };

        issue(0, 0); issue(1, 1); issue(2, 2);
        float d[4][4] = {};

        #pragma unroll 1
        for (int kc = 0; kc < NK; kc++) {
            CP_WAIT(2);
            __syncthreads();
            if (kc + 3 < NK) issue((kc + 3) & 3, kc + 3);
            const int s = (kc & 3) * SLOT;
            compute_stage(pAh + s, pAl + s, pBh + s, pBl + s, wm, wn, g, tg, d);
        }
        CP_WAIT(0);   // drain own groups before next t reuses slots

        // epilogue: h = tanh(xin + acc); store fp32 + hi/lo split
        const int r0 = rowBase + wm * 16 + g;
        const int r1 = r0 + 8;
        #pragma unroll
        for (int j = 0; j < 4; j++) {
            const int col = colBase + wn * 32 + j * 8 + 2 * tg;
            const size_t o0 = ((size_t)t * B_ + r0) * H_ + col;
            const size_t o1 = ((size_t)t * B_ + r1) * H_ + col;
            float2 x0 = *(const float2*)&g_xin[o0];
            float2 x1 = *(const float2*)&g_xin[o1];
            float h00 = tanhf(x0.x + d[j][0]);
            float h01 = tanhf(x0.y + d[j][1]);
            float h10 = tanhf(x1.x + d[j][2]);
            float h11 = tanhf(x1.y + d[j][3]);
            *(float2*)&g_hall[o0] = make_float2(h00, h01);
            *(float2*)&g_hall[o1] = make_float2(h10, h11);
            __nv_bfloat16 e0, f0, e1, f1, e2, f2, e3, f3;
            split2(h00, e0, f0); split2(h01, e1, f1);
            split2(h10, e2, f2); split2(h11, e3, f3);
            const size_t w0 = (size_t)r0 * H_ + col;
            const size_t w1 = (size_t)r1 * H_ + col;
            *(__nv_bfloat162*)&whi[w0] = __halves2bfloat162(e0, e1);
            *(__nv_bfloat162*)&wlo[w0] = __halves2bfloat162(f0, f1);
            *(__nv_bfloat162*)&whi[w1] = __halves2bfloat162(e2, e3);
            *(__nv_bfloat162*)&wlo[w1] = __halves2bfloat162(f2, f3);
        }

        if (t < T_ - 1) grid_barrier(base + (unsigned)t + 1u);
    }
}

// ---------------------------------------------------------------------------
// Output head
// ---------------------------------------------------------------------------
__global__ void __launch_bounds__(256) out_kernel(
    const float* __restrict__ lin_w,
    const float* __restrict__ lin_b,
    float* __restrict__ out)
{
    const int bt = blockIdx.x;
    const int t = bt / B_;
    const int b = bt % B_;
    const int tid = threadIdx.x;

    const float* hrow = g_hall + ((size_t)t * B_ + b) * H_;

    float hreg[H_ / 256];
    #pragma unroll
    for (int i = 0; i < H_ / 256; i++)
        hreg[i] = hrow[i * 256 + tid];

    float acc[O_];
    #pragma unroll
    for (int o = 0; o < O_; o++) {
        float s = 0.f;
        #pragma unroll
        for (int i = 0; i < H_ / 256; i++)
            s += hreg[i] * lin_w[(size_t)o * H_ + i * 256 + tid];
        acc[o] = s;
    }

    #pragma unroll
    for (int off = 16; off > 0; off >>= 1)
        #pragma unroll
        for (int o = 0; o < O_; o++)
            acc[o] += __shfl_xor_sync(0xFFFFFFFFu, acc[o], off);

    __shared__ float wsum[8][O_];
    const int lane = tid & 31;
    const int w = tid >> 5;
    if (lane == 0)
        #pragma unroll
        for (int o = 0; o < O_; o++)
            wsum[w][o] = acc[o];
    __syncthreads();

    if (tid < O_) {
        float s = lin_b[tid];
        #pragma unroll
        for (int ww = 0; ww < 8; ww++)
            s += wsum[ww][tid];
        out[((size_t)b * T_ + t) * O_ + tid] = s;
    }
}

// ---------------------------------------------------------------------------
extern "C" void kernel_launch(void* const* d_in, const int* in_sizes, int n_in,
                              void* d_out, int out_size)
{
    const float* x     = (const float*)d_in[0];
    const float* h0    = (const float*)d_in[1];
    const float* Win   = (const float*)d_in[2];
    const float* W     = (const float*)d_in[3];
    const float* lin_w = (const float*)d_in[4];
    const float* lin_b = (const float*)d_in[5];
    float* out = (float*)d_out;

    __nv_bfloat16 *xhi, *xlo, *winT_hi, *winT_lo, *wT_hi, *wT_lo, *hA_hi, *hA_lo;
    cudaGetSymbolAddress((void**)&xhi, g_xhi);
    cudaGetSymbolAddress((void**)&xlo, g_xlo);
    cudaGetSymbolAddress((void**)&winT_hi, g_WinT_hi);
    cudaGetSymbolAddress((void**)&winT_lo, g_WinT_lo);
    cudaGetSymbolAddress((void**)&wT_hi, g_WT_hi);
    cudaGetSymbolAddress((void**)&wT_lo, g_WT_lo);
    cudaGetSymbolAddress((void**)&hA_hi, g_hA_hi);
    cudaGetSymbolAddress((void**)&hA_lo, g_hA_lo);

    static bool attr_done = false;
    if (!attr_done) {
        cudaFuncSetAttribute(xin_gemm_kernel,
                             cudaFuncAttributeMaxDynamicSharedMemorySize, SMEM_BYTES);
        cudaFuncSetAttribute(step_persistent_kernel,
                             cudaFuncAttributeMaxDynamicSharedMemorySize, SMEM_BYTES);
        attr_done = true;
    }

    // Prologue: splits + weight transposes
    decomp_kernel<<<4096, 256>>>(x, xhi, xlo, (size_t)M1 * I_ / 4);
    decomp_kernel<<<512, 256>>>(h0, hA_hi, hA_lo, (size_t)B_ * H_ / 4);
    transpose_decomp_kernel<<<dim3(H_ / 32, I_ / 32), dim3(32, 8)>>>(Win, I_, H_, winT_hi, winT_lo);
    transpose_decomp_kernel<<<dim3(H_ / 32, H_ / 32), dim3(32, 8)>>>(W, H_, H_, wT_hi, wT_lo);

    // Input projection
    xin_gemm_kernel<<<dim3(H_ / BN, M1 / BM), 256, SMEM_BYTES>>>();

    // Full recurrence in one persistent kernel
    step_persistent_kernel<<<NBLK_STEP, 256, SMEM_BYTES>>>();

    // Output head
    out_kernel<<<T_ * B_, 256>>>(lin_w, lin_b, out);
}